// round 9
// baseline (speedup 1.0000x reference)
#include <cuda_runtime.h>
#include <math.h>

#define EPSF      1e-10f
#define SIGINV    7000.0f
#define HEIGHT    256
#define WIDTH     256
#define MAXF      256
#define MAXP      1024
// logf(1e-10f)
#define LOGMIN    -23.025850929940457f
// band where log-miss contribution is non-negligible: sqrt(18/7000) ~= 0.050709
#define BANDEXP   0.0508f

// per-face precomputed data, COMPACTED to valid faces only (scratch; no allocs)
__device__ float4 g_f0[MAXF];    // x0,y0,x1,y1
__device__ float4 g_f1[MAXF];    // x2,y2,z0,z1
__device__ float4 g_f2[MAXF];    // z2, invA, inv01, inv12
__device__ float  g_i20[MAXF];   // inv20
__device__ float4 g_bb[MAXF];    // expanded bbox: xlo,ylo,xhi,yhi
__device__ float4 g_uva[MAXF];   // u0,v0,u1,v1
__device__ float2 g_uvb[MAXF];   // u2,v2
__device__ int    g_Fc;          // number of valid faces after compaction

// XLA-style contraction of a*b - c*d: fuse the FIRST multiply.
__device__ __forceinline__ float fused_det(float a, float b, float c, float d) {
    return __fmaf_rn(a, b, -__fmul_rn(c, d));
}

__global__ void face_kernel(const float* __restrict__ pts,
                            const int*   __restrict__ faces,
                            const float* __restrict__ rot,
                            const float* __restrict__ cpos,
                            const float* __restrict__ cproj,
                            const float* __restrict__ uv,
                            const int*   __restrict__ ft,
                            float* __restrict__ out,
                            int P, int F, int normal_off) {
    __shared__ float sp[MAXP][3];   // camera-space points
    __shared__ float sxy[MAXP][2];  // projected 2D
    __shared__ int   wbase[9];      // per-warp compaction offsets

    int t = threadIdx.x;
    for (int p = t; p < P; p += blockDim.x) {
        float a0 = __fsub_rn(pts[p * 3 + 0], cpos[0]);
        float a1 = __fsub_rn(pts[p * 3 + 1], cpos[1]);
        float a2 = __fsub_rn(pts[p * 3 + 2], cpos[2]);
        float q0 = __fmaf_rn(a2, rot[2], __fmaf_rn(a1, rot[1], __fmul_rn(a0, rot[0])));
        float q1 = __fmaf_rn(a2, rot[5], __fmaf_rn(a1, rot[4], __fmul_rn(a0, rot[3])));
        float q2 = __fmaf_rn(a2, rot[8], __fmaf_rn(a1, rot[7], __fmul_rn(a0, rot[6])));
        sp[p][0] = q0; sp[p][1] = q1; sp[p][2] = q2;
        float x3 = __fmul_rn(q0, cproj[0]);
        float y3 = __fmul_rn(q1, cproj[1]);
        float z3 = __fmul_rn(q2, cproj[2]);
        sxy[p][0] = __fdiv_rn(x3, z3);
        sxy[p][1] = __fdiv_rn(y3, z3);
    }
    __syncthreads();

    // one thread per face (F <= 256)
    int f = t;
    bool have = f < F;

    float x0=0,y0=0,x1=0,y1=0,x2=0,y2=0,p0z=0,p1z=0,p2z=0,invA=0;
    bool valid = false;

    if (have) {
        int i0 = faces[f * 3 + 0], i1 = faces[f * 3 + 1], i2 = faces[f * 3 + 2];
        float p0x = sp[i0][0], p0y = sp[i0][1]; p0z = sp[i0][2];
        float p1x = sp[i1][0], p1y = sp[i1][1]; p1z = sp[i1][2];
        float p2x = sp[i2][0], p2y = sp[i2][1]; p2z = sp[i2][2];
        x0 = sxy[i0][0]; y0 = sxy[i0][1];
        x1 = sxy[i1][0]; y1 = sxy[i1][1];
        x2 = sxy[i2][0]; y2 = sxy[i2][1];

        // normal = cross(p1-p0, p2-p0) with XLA-style fma contraction.
        float d1x = __fsub_rn(p1x, p0x), d1y = __fsub_rn(p1y, p0y), d1z = __fsub_rn(p1z, p0z);
        float d2x = __fsub_rn(p2x, p0x), d2y = __fsub_rn(p2y, p0y), d2z = __fsub_rn(p2z, p0z);
        float nx = fused_det(d1y, d2z, d1z, d2y);
        float ny = fused_det(d1z, d2x, d1x, d2z);
        float nz = fused_det(d1x, d2y, d1y, d2x);
        float ss = __fmaf_rn(nz, nz, __fmaf_rn(ny, ny, __fmul_rn(nx, nx)));
        float nn = __fsqrt_rn(ss);
        float den = __fadd_rn(nn, EPSF);
        out[normal_off + f * 3 + 0] = __fdiv_rn(nx, den);
        out[normal_off + f * 3 + 1] = __fdiv_rn(ny, den);
        out[normal_off + f * 3 + 2] = __fdiv_rn(nz, den);

        float A = fused_det(__fsub_rn(x1, x0), __fsub_rn(y2, y0),
                            __fsub_rn(x2, x0), __fsub_rn(y1, y0));
        bool aok = fabsf(A) > EPSF;
        invA = aok ? __fdiv_rn(1.0f, A) : 0.0f;
        valid = aok && (nz > 0.0f);
    }

    // order-preserving block-wide compaction of valid faces
    unsigned m = __ballot_sync(0xffffffffu, valid);
    int lane = t & 31, warp = t >> 5;
    int pre = __popc(m & ((1u << lane) - 1u));
    if (lane == 0) wbase[warp + 1] = __popc(m);
    __syncthreads();
    if (t == 0) {
        wbase[0] = 0;
        for (int w = 0; w < 8; w++) wbase[w + 1] += wbase[w];
        g_Fc = wbase[8];
    }
    __syncthreads();

    if (valid) {
        int c = wbase[warp] + pre;
        float e01x = x1 - x0, e01y = y1 - y0;
        float e12x = x2 - x1, e12y = y2 - y1;
        float e20x = x0 - x2, e20y = y0 - y2;
        float i01 = 1.0f / (e01x * e01x + e01y * e01y + EPSF);
        float i12 = 1.0f / (e12x * e12x + e12y * e12y + EPSF);
        float i20 = 1.0f / (e20x * e20x + e20y * e20y + EPSF);
        g_f0[c]  = make_float4(x0, y0, x1, y1);
        g_f1[c]  = make_float4(x2, y2, p0z, p1z);
        g_f2[c]  = make_float4(p2z, invA, i01, i12);
        g_i20[c] = i20;
        // expanded bbox: outside it, point-to-triangle dist > band -> aa >= 18
        float xlo = fminf(x0, fminf(x1, x2)) - BANDEXP;
        float xhi = fmaxf(x0, fmaxf(x1, x2)) + BANDEXP;
        float ylo = fminf(y0, fminf(y1, y2)) - BANDEXP;
        float yhi = fmaxf(y0, fmaxf(y1, y2)) + BANDEXP;
        g_bb[c] = make_float4(xlo, ylo, xhi, yhi);
        int t0 = ft[f * 3 + 0], t1 = ft[f * 3 + 1], t2 = ft[f * 3 + 2];
        g_uva[c] = make_float4(uv[t0 * 2], uv[t0 * 2 + 1], uv[t1 * 2], uv[t1 * 2 + 1]);
        g_uvb[c] = make_float2(uv[t2 * 2], uv[t2 * 2 + 1]);
    }
}

__device__ __forceinline__ float edge_d2(float rx, float ry,
                                         float ex, float ey, float inv) {
    float tt = __saturatef((rx * ex + ry * ey) * inv);
    float dx = rx - tt * ex;
    float dy = ry - tt * ey;
    return dx * dx + dy * dy;
}

// Tiled raster: block = 8x8 pixel tile x 8 warp-pure face-chunks (512 thr,
// 4 CTAs/SM = 64 warps/SM at <=32 regs). chunk = t>>6 (2 warps each) ->
// face index warp-uniform -> all shared loads are broadcasts. Per block:
// prefilter faces vs tile bbox (order-preserving compaction into shared),
// chunks walk disjoint sublists, combine via smem (ascending chunk order +
// strict > == argmax first-occurrence).
__global__ void __launch_bounds__(512, 4)
raster_kernel(const float* __restrict__ tex, float* __restrict__ out,
              int th, int tw) {
    __shared__ float4 s0[MAXF], s1[MAXF], s2[MAXF];
    __shared__ float  si[MAXF];
    __shared__ int    sidx[MAXF];
    __shared__ int    wbase[9];
    __shared__ float  racc[8][64], rz[8][64], rw0[8][64], rw1[8][64];
    __shared__ int    rk[8][64];

    int t = threadIdx.x;
    int Fc = g_Fc;

    // tile pixel-center bounds (32x32 tiles of 8x8 px)
    int ti = blockIdx.x >> 5;   // tile row
    int tj = blockIdx.x & 31;   // tile col
    float txlo = ((float)(tj * 8) + 0.5f) * (1.0f / 128.0f) - 1.0f;
    float txhi = ((float)(tj * 8 + 7) + 0.5f) * (1.0f / 128.0f) - 1.0f;
    float tyhi = 1.0f - (((float)(ti * 8) + 0.5f) * (1.0f / 128.0f));
    float tylo = 1.0f - (((float)(ti * 8 + 7) + 0.5f) * (1.0f / 128.0f));

    // prefilter: warps 0..7 cover all <=256 faces in one round
    int lane = t & 31, warp = t >> 5;
    bool keep = false;
    if (t < Fc) {
        float4 bb = g_bb[t];
        keep = !(bb.z < txlo || bb.x > txhi || bb.w < tylo || bb.y > tyhi);
    }
    unsigned m = __ballot_sync(0xffffffffu, keep);
    if (warp < 8 && lane == 0) wbase[warp + 1] = __popc(m);
    __syncthreads();
    if (t == 0) {
        wbase[0] = 0;
        #pragma unroll
        for (int w = 0; w < 8; w++) wbase[w + 1] += wbase[w];
    }
    __syncthreads();
    if (keep) {
        int c = wbase[warp] + __popc(m & ((1u << lane) - 1u));
        s0[c] = g_f0[t]; s1[c] = g_f1[t]; s2[c] = g_f2[t];
        si[c] = g_i20[t]; sidx[c] = t;
    }
    __syncthreads();
    int ns = wbase[8];

    // this thread's pixel + face chunk (chunk = t>>6: two warps, warp-pure)
    int p = t & 63;             // pixel within tile
    int chunk = t >> 6;         // 0..7
    int row = ti * 8 + (p >> 3);
    int col = tj * 8 + (p & 7);
    float px = ((float)col + 0.5f) * (1.0f / 128.0f) - 1.0f;
    float py = 1.0f - ((float)row + 0.5f) * (1.0f / 128.0f);

    int q = (ns + 7) >> 3;
    int kbeg = chunk * q;
    int kend = min(kbeg + q, ns);

    float acc = 0.0f;
    int   cnt = 0;
    float bz = -1e10f, bw0 = 0.0f, bw1 = 0.0f;
    int bk = -1;

    for (int k = kbeg; k < kend; k++) {
        float4 A4 = s0[k];
        float4 B4 = s1[k];
        float4 C4 = s2[k];
        float r0x = __fsub_rn(px, A4.x), r0y = __fsub_rn(py, A4.y);
        float r1x = __fsub_rn(px, A4.z), r1y = __fsub_rn(py, A4.w);
        float r2x = __fsub_rn(px, B4.x), r2y = __fsub_rn(py, B4.y);
        float invA = C4.y;
        float w0 = __fmul_rn(fused_det(r1x, r2y, r2x, r1y), invA);
        float w1 = __fmul_rn(fused_det(r2x, r0y, r0x, r2y), invA);
        float w2 = __fsub_rn(__fsub_rn(1.0f, w0), w1);
        bool inside = (w0 >= 0.0f) && (w1 >= 0.0f) && (w2 >= 0.0f);

        if (inside) {
            float z = __fmaf_rn(w2, C4.x, __fmaf_rn(w0, B4.z, __fmul_rn(w1, B4.w)));
            if (z > bz) { bz = z; bk = k; bw0 = w0; bw1 = w1; }
            cnt++;
        } else {
            // edge vectors from r's: e_ab = r_a - r_b == v_b - v_a (<=1ulp)
            float e01x = r0x - r1x, e01y = r0y - r1y;
            float e12x = r1x - r2x, e12y = r1y - r2y;
            float e20x = r2x - r0x, e20y = r2y - r0y;
            float d2 = edge_d2(r0x, r0y, e01x, e01y, C4.z);
            d2 = fminf(d2, edge_d2(r1x, r1y, e12x, e12y, C4.w));
            d2 = fminf(d2, edge_d2(r2x, r2y, e20x, e20y, si[k]));
            float aa = d2 * SIGINV;
            if (aa < 18.0f) {
                acc += logf(fmaxf(1.0f - expf(-aa), 1e-10f));
            }
        }
    }
    acc += (float)cnt * LOGMIN;

    racc[chunk][p] = acc;
    rz[chunk][p] = bz; rw0[chunk][p] = bw0; rw1[chunk][p] = bw1; rk[chunk][p] = bk;
    __syncthreads();

    if (t < 64) {
        float facc = racc[0][t];
        float fz = rz[0][t], fw0 = rw0[0][t], fw1 = rw1[0][t];
        int fk = rk[0][t];
        #pragma unroll
        for (int c = 1; c < 8; c++) {
            facc += racc[c][t];
            float oz = rz[c][t];
            // ascending chunk order -> strict > keeps first occurrence
            if (oz > fz) { fz = oz; fk = rk[c][t]; fw0 = rw0[c][t]; fw1 = rw1[c][t]; }
        }

        int prow = ti * 8 + (t >> 3);
        int pcol = tj * 8 + (t & 7);
        int pix = prow * 256 + pcol;

        // improb
        out[HEIGHT * WIDTH * 3 + pix] = 1.0f - expf(facc);

        // fragment shader
        float c0 = 0.0f, c1 = 0.0f, c2 = 0.0f;
        if (fk >= 0) {
            int bf = sidx[fk];
            float fw2 = __fsub_rn(__fsub_rn(1.0f, fw0), fw1);
            float4 U  = __ldg(&g_uva[bf]);
            float2 U2 = __ldg(&g_uvb[bf]);
            float u = __fmaf_rn(fw2, U2.x, __fmaf_rn(fw0, U.x, __fmul_rn(fw1, U.z)));
            float v = __fmaf_rn(fw2, U2.y, __fmaf_rn(fw0, U.y, __fmul_rn(fw1, U.w)));
            float mask = __fadd_rn(__fadd_rn(fw0, fw1), fw2);

            float x = u * (float)(tw - 1);
            float y = (1.0f - v) * (float)(th - 1);
            float x0f = fminf(fmaxf(floorf(x), 0.0f), (float)(tw - 1));
            float y0f = fminf(fmaxf(floorf(y), 0.0f), (float)(th - 1));
            int x0i = (int)x0f, y0i = (int)y0f;
            int x1i = min(x0i + 1, tw - 1);
            int y1i = min(y0i + 1, th - 1);
            float wx = fminf(fmaxf(x - x0f, 0.0f), 1.0f);
            float wy = fminf(fmaxf(y - y0f, 0.0f), 1.0f);

            int cs = th * tw;
            int b00 = y0i * tw + x0i, b01 = y0i * tw + x1i;
            int b10 = y1i * tw + x0i, b11 = y1i * tw + x1i;

            float col3[3];
            #pragma unroll
            for (int ch = 0; ch < 3; ch++) {
                const float* tc = tex + ch * cs;
                float v00 = __ldg(tc + b00), v01 = __ldg(tc + b01);
                float v10 = __ldg(tc + b10), v11 = __ldg(tc + b11);
                float cc = (v00 * (1.0f - wx) + v01 * wx) * (1.0f - wy)
                         + (v10 * (1.0f - wx) + v11 * wx) * wy;
                col3[ch] = fminf(fmaxf(cc * mask, 0.0f), 1.0f);
            }
            c0 = col3[0]; c1 = col3[1]; c2 = col3[2];
        }
        out[pix * 3 + 0] = c0;
        out[pix * 3 + 1] = c1;
        out[pix * 3 + 2] = c2;
    }
}

extern "C" void kernel_launch(void* const* d_in, const int* in_sizes, int n_in,
                              void* d_out, int out_size) {
    const float* pts   = (const float*)d_in[0];
    const int*   faces = (const int*)  d_in[1];
    const float* rot   = (const float*)d_in[2];
    const float* cpos  = (const float*)d_in[3];
    const float* cproj = (const float*)d_in[4];
    const float* uv    = (const float*)d_in[5];
    const int*   ft    = (const int*)  d_in[6];
    const float* tex   = (const float*)d_in[7];

    int P = in_sizes[0] / 3;
    int F = in_sizes[1] / 3;
    int texels = in_sizes[7] / 3;
    int tw = (int)(sqrt((double)texels) + 0.5);
    int th = texels / tw;

    float* out = (float*)d_out;
    int normal_off = HEIGHT * WIDTH * 3 + HEIGHT * WIDTH;

    face_kernel<<<1, 256>>>(pts, faces, rot, cpos, cproj, uv, ft, out, P, F, normal_off);
    // 32x32 tiles of 8x8 pixels, 8 face-chunks per tile
    raster_kernel<<<1024, 512>>>(tex, out, th, tw);
}

// round 10
// speedup vs baseline: 1.4168x; 1.4168x over previous
#include <cuda_runtime.h>
#include <math.h>

#define EPSF      1e-10f
#define SIGINV    7000.0f
#define HEIGHT    256
#define WIDTH     256
#define MAXF      256
#define MAXP      1024
// logf(1e-10f)
#define LOGMIN    -23.025850929940457f
// band where log-miss contribution is non-negligible: sqrt(18/7000) ~= 0.050709
#define BANDEXP   0.0508f
// edge-line cull threshold: band + tile half-diagonal (3.5*sqrt(2)/128) + margin
#define CULLTHR   (0.0508f + 0.03867f + 0.002f)

// per-face precomputed data, COMPACTED to valid faces only (scratch; no allocs)
__device__ float4 g_f0[MAXF];    // x0,y0,x1,y1
__device__ float4 g_f1[MAXF];    // x2,y2,z0,z1
__device__ float4 g_f2[MAXF];    // z2, invA, inv01, inv12
__device__ float  g_i20[MAXF];   // inv20
__device__ float4 g_bb[MAXF];    // expanded bbox: xlo,ylo,xhi,yhi
__device__ float4 g_uva[MAXF];   // u0,v0,u1,v1
__device__ float2 g_uvb[MAXF];   // u2,v2
__device__ int    g_Fc;          // number of valid faces after compaction

// XLA-style contraction of a*b - c*d: fuse the FIRST multiply.
__device__ __forceinline__ float fused_det(float a, float b, float c, float d) {
    return __fmaf_rn(a, b, -__fmul_rn(c, d));
}

__global__ void face_kernel(const float* __restrict__ pts,
                            const int*   __restrict__ faces,
                            const float* __restrict__ rot,
                            const float* __restrict__ cpos,
                            const float* __restrict__ cproj,
                            const float* __restrict__ uv,
                            const int*   __restrict__ ft,
                            float* __restrict__ out,
                            int P, int F, int normal_off) {
    __shared__ float sp[MAXP][3];   // camera-space points
    __shared__ float sxy[MAXP][2];  // projected 2D
    __shared__ int   wbase[9];      // per-warp compaction offsets

    int t = threadIdx.x;
    for (int p = t; p < P; p += blockDim.x) {
        float a0 = __fsub_rn(pts[p * 3 + 0], cpos[0]);
        float a1 = __fsub_rn(pts[p * 3 + 1], cpos[1]);
        float a2 = __fsub_rn(pts[p * 3 + 2], cpos[2]);
        float q0 = __fmaf_rn(a2, rot[2], __fmaf_rn(a1, rot[1], __fmul_rn(a0, rot[0])));
        float q1 = __fmaf_rn(a2, rot[5], __fmaf_rn(a1, rot[4], __fmul_rn(a0, rot[3])));
        float q2 = __fmaf_rn(a2, rot[8], __fmaf_rn(a1, rot[7], __fmul_rn(a0, rot[6])));
        sp[p][0] = q0; sp[p][1] = q1; sp[p][2] = q2;
        float x3 = __fmul_rn(q0, cproj[0]);
        float y3 = __fmul_rn(q1, cproj[1]);
        float z3 = __fmul_rn(q2, cproj[2]);
        sxy[p][0] = __fdiv_rn(x3, z3);
        sxy[p][1] = __fdiv_rn(y3, z3);
    }
    __syncthreads();

    // one thread per face (F <= 256)
    int f = t;
    bool have = f < F;

    float x0=0,y0=0,x1=0,y1=0,x2=0,y2=0,p0z=0,p1z=0,p2z=0,invA=0;
    bool valid = false;

    if (have) {
        int i0 = faces[f * 3 + 0], i1 = faces[f * 3 + 1], i2 = faces[f * 3 + 2];
        float p0x = sp[i0][0], p0y = sp[i0][1]; p0z = sp[i0][2];
        float p1x = sp[i1][0], p1y = sp[i1][1]; p1z = sp[i1][2];
        float p2x = sp[i2][0], p2y = sp[i2][1]; p2z = sp[i2][2];
        x0 = sxy[i0][0]; y0 = sxy[i0][1];
        x1 = sxy[i1][0]; y1 = sxy[i1][1];
        x2 = sxy[i2][0]; y2 = sxy[i2][1];

        // normal = cross(p1-p0, p2-p0) with XLA-style fma contraction.
        float d1x = __fsub_rn(p1x, p0x), d1y = __fsub_rn(p1y, p0y), d1z = __fsub_rn(p1z, p0z);
        float d2x = __fsub_rn(p2x, p0x), d2y = __fsub_rn(p2y, p0y), d2z = __fsub_rn(p2z, p0z);
        float nx = fused_det(d1y, d2z, d1z, d2y);
        float ny = fused_det(d1z, d2x, d1x, d2z);
        float nz = fused_det(d1x, d2y, d1y, d2x);
        float ss = __fmaf_rn(nz, nz, __fmaf_rn(ny, ny, __fmul_rn(nx, nx)));
        float nn = __fsqrt_rn(ss);
        float den = __fadd_rn(nn, EPSF);
        out[normal_off + f * 3 + 0] = __fdiv_rn(nx, den);
        out[normal_off + f * 3 + 1] = __fdiv_rn(ny, den);
        out[normal_off + f * 3 + 2] = __fdiv_rn(nz, den);

        float A = fused_det(__fsub_rn(x1, x0), __fsub_rn(y2, y0),
                            __fsub_rn(x2, x0), __fsub_rn(y1, y0));
        bool aok = fabsf(A) > EPSF;
        invA = aok ? __fdiv_rn(1.0f, A) : 0.0f;
        valid = aok && (nz > 0.0f);
    }

    // order-preserving block-wide compaction of valid faces
    unsigned m = __ballot_sync(0xffffffffu, valid);
    int lane = t & 31, warp = t >> 5;
    int pre = __popc(m & ((1u << lane) - 1u));
    if (lane == 0) wbase[warp + 1] = __popc(m);
    __syncthreads();
    if (t == 0) {
        wbase[0] = 0;
        for (int w = 0; w < 8; w++) wbase[w + 1] += wbase[w];
        g_Fc = wbase[8];
    }
    __syncthreads();

    if (valid) {
        int c = wbase[warp] + pre;
        float e01x = x1 - x0, e01y = y1 - y0;
        float e12x = x2 - x1, e12y = y2 - y1;
        float e20x = x0 - x2, e20y = y0 - y2;
        float i01 = 1.0f / (e01x * e01x + e01y * e01y + EPSF);
        float i12 = 1.0f / (e12x * e12x + e12y * e12y + EPSF);
        float i20 = 1.0f / (e20x * e20x + e20y * e20y + EPSF);
        g_f0[c]  = make_float4(x0, y0, x1, y1);
        g_f1[c]  = make_float4(x2, y2, p0z, p1z);
        g_f2[c]  = make_float4(p2z, invA, i01, i12);
        g_i20[c] = i20;
        // expanded bbox: outside it, point-to-triangle dist > band -> aa >= 18
        float xlo = fminf(x0, fminf(x1, x2)) - BANDEXP;
        float xhi = fmaxf(x0, fmaxf(x1, x2)) + BANDEXP;
        float ylo = fminf(y0, fminf(y1, y2)) - BANDEXP;
        float yhi = fmaxf(y0, fmaxf(y1, y2)) + BANDEXP;
        g_bb[c] = make_float4(xlo, ylo, xhi, yhi);
        int t0 = ft[f * 3 + 0], t1 = ft[f * 3 + 1], t2 = ft[f * 3 + 2];
        g_uva[c] = make_float4(uv[t0 * 2], uv[t0 * 2 + 1], uv[t1 * 2], uv[t1 * 2 + 1]);
        g_uvb[c] = make_float2(uv[t2 * 2], uv[t2 * 2 + 1]);
    }
}

__device__ __forceinline__ float edge_d2(float rx, float ry,
                                         float ex, float ey, float inv) {
    float tt = __saturatef((rx * ex + ry * ey) * inv);
    float dx = rx - tt * ex;
    float dy = ry - tt * ey;
    return dx * dx + dy * dy;
}

// Tiled raster: block = 8x8 pixel tile x 4 warp-pure face-chunks (256 thr).
// Prefilter: bbox overlap AND edge-line distance cull (conservative lower
// bound on point-to-triangle distance from the tile center: for a convex
// triangle dist >= max_e outward signed line distance; sqrt(1/(e^2+eps))
// underestimates 1/|e| -> underestimates distance -> never over-culls;
// tiles touching/inside the triangle have d<=0 and are always kept).
__global__ void __launch_bounds__(256)
raster_kernel(const float* __restrict__ tex, float* __restrict__ out,
              int th, int tw) {
    __shared__ float4 s0[MAXF], s1[MAXF], s2[MAXF];
    __shared__ float  si[MAXF];
    __shared__ int    sidx[MAXF];
    __shared__ int    wbase[9];
    __shared__ float  racc[4][64], rz[4][64], rw0[4][64], rw1[4][64];
    __shared__ int    rk[4][64];

    int t = threadIdx.x;
    int Fc = g_Fc;

    // tile pixel-center bounds (32x32 tiles of 8x8 px)
    int ti = blockIdx.x >> 5;   // tile row
    int tj = blockIdx.x & 31;   // tile col
    float txlo = ((float)(tj * 8) + 0.5f) * (1.0f / 128.0f) - 1.0f;
    float txhi = ((float)(tj * 8 + 7) + 0.5f) * (1.0f / 128.0f) - 1.0f;
    float tyhi = 1.0f - (((float)(ti * 8) + 0.5f) * (1.0f / 128.0f));
    float tylo = 1.0f - (((float)(ti * 8 + 7) + 0.5f) * (1.0f / 128.0f));
    float pcx = 0.5f * (txlo + txhi);
    float pcy = 0.5f * (tylo + tyhi);

    // prefilter: one face per thread
    bool keep = false;
    if (t < Fc) {
        float4 bb = g_bb[t];
        keep = !(bb.z < txlo || bb.x > txhi || bb.w < tylo || bb.y > tyhi);
        if (keep) {
            float4 F0 = g_f0[t];
            float4 F1 = g_f1[t];
            float4 F2 = g_f2[t];
            float i20v = g_i20[t];
            float sA = (F2.y > 0.0f) ? 1.0f : -1.0f;
            float e01x = F0.z - F0.x, e01y = F0.w - F0.y;
            float e12x = F1.x - F0.z, e12y = F1.y - F0.w;
            float e20x = F0.x - F1.x, e20y = F0.y - F1.y;
            float c01 = e01x * (pcy - F0.y) - e01y * (pcx - F0.x);
            float c12 = e12x * (pcy - F0.w) - e12y * (pcx - F0.z);
            float c20 = e20x * (pcy - F1.y) - e20y * (pcx - F1.x);
            float d01 = -sA * c01 * sqrtf(F2.z);
            float d12 = -sA * c12 * sqrtf(F2.w);
            float d20 = -sA * c20 * sqrtf(i20v);
            float dmax = fmaxf(d01, fmaxf(d12, d20));
            keep = dmax <= CULLTHR;
        }
    }
    unsigned m = __ballot_sync(0xffffffffu, keep);
    int lane = t & 31, warp = t >> 5;
    int pre = __popc(m & ((1u << lane) - 1u));
    if (lane == 0) wbase[warp + 1] = __popc(m);
    __syncthreads();
    if (t == 0) {
        wbase[0] = 0;
        for (int w = 0; w < 8; w++) wbase[w + 1] += wbase[w];
    }
    __syncthreads();
    if (keep) {
        int c = wbase[warp] + pre;
        s0[c] = g_f0[t]; s1[c] = g_f1[t]; s2[c] = g_f2[t];
        si[c] = g_i20[t]; sidx[c] = t;
    }
    __syncthreads();
    int ns = wbase[8];

    // this thread's pixel + face chunk
    int p = t & 63;             // pixel within tile
    int chunk = t >> 6;         // 0..3; warp-pure
    int row = ti * 8 + (p >> 3);
    int col = tj * 8 + (p & 7);
    float px = ((float)col + 0.5f) * (1.0f / 128.0f) - 1.0f;
    float py = 1.0f - ((float)row + 0.5f) * (1.0f / 128.0f);

    int q = (ns + 3) >> 2;
    int kbeg = chunk * q;
    int kend = min(kbeg + q, ns);

    float acc = 0.0f;
    int   cnt = 0;
    float bz = -1e10f, bw0 = 0.0f, bw1 = 0.0f;
    int bk = -1;

    for (int k = kbeg; k < kend; k++) {
        float4 A4 = s0[k];
        float4 B4 = s1[k];
        float4 C4 = s2[k];
        float r0x = __fsub_rn(px, A4.x), r0y = __fsub_rn(py, A4.y);
        float r1x = __fsub_rn(px, A4.z), r1y = __fsub_rn(py, A4.w);
        float r2x = __fsub_rn(px, B4.x), r2y = __fsub_rn(py, B4.y);
        float invA = C4.y;
        float w0 = __fmul_rn(fused_det(r1x, r2y, r2x, r1y), invA);
        float w1 = __fmul_rn(fused_det(r2x, r0y, r0x, r2y), invA);
        float w2 = __fsub_rn(__fsub_rn(1.0f, w0), w1);
        bool inside = (w0 >= 0.0f) && (w1 >= 0.0f) && (w2 >= 0.0f);

        if (inside) {
            float z = __fmaf_rn(w2, C4.x, __fmaf_rn(w0, B4.z, __fmul_rn(w1, B4.w)));
            if (z > bz) { bz = z; bk = k; bw0 = w0; bw1 = w1; }
            cnt++;
        } else {
            // edge vectors from r's: e_ab = r_a - r_b == v_b - v_a (<=1ulp)
            float e01x = r0x - r1x, e01y = r0y - r1y;
            float e12x = r1x - r2x, e12y = r1y - r2y;
            float e20x = r2x - r0x, e20y = r2y - r0y;
            float d2 = edge_d2(r0x, r0y, e01x, e01y, C4.z);
            d2 = fminf(d2, edge_d2(r1x, r1y, e12x, e12y, C4.w));
            d2 = fminf(d2, edge_d2(r2x, r2y, e20x, e20y, si[k]));
            float aa = d2 * SIGINV;
            if (aa < 18.0f) {
                acc += logf(fmaxf(1.0f - expf(-aa), 1e-10f));
            }
        }
    }
    acc += (float)cnt * LOGMIN;

    racc[chunk][p] = acc;
    rz[chunk][p] = bz; rw0[chunk][p] = bw0; rw1[chunk][p] = bw1; rk[chunk][p] = bk;
    __syncthreads();

    if (t < 64) {
        float facc = racc[0][t];
        float fz = rz[0][t], fw0 = rw0[0][t], fw1 = rw1[0][t];
        int fk = rk[0][t];
        #pragma unroll
        for (int c = 1; c < 4; c++) {
            facc += racc[c][t];
            float oz = rz[c][t];
            // ascending chunk order -> strict > keeps first occurrence
            if (oz > fz) { fz = oz; fk = rk[c][t]; fw0 = rw0[c][t]; fw1 = rw1[c][t]; }
        }

        int prow = ti * 8 + (t >> 3);
        int pcol = tj * 8 + (t & 7);
        int pix = prow * 256 + pcol;

        // improb
        out[HEIGHT * WIDTH * 3 + pix] = 1.0f - expf(facc);

        // fragment shader
        float c0 = 0.0f, c1 = 0.0f, c2 = 0.0f;
        if (fk >= 0) {
            int bf = sidx[fk];
            float fw2 = __fsub_rn(__fsub_rn(1.0f, fw0), fw1);
            float4 U  = __ldg(&g_uva[bf]);
            float2 U2 = __ldg(&g_uvb[bf]);
            float u = __fmaf_rn(fw2, U2.x, __fmaf_rn(fw0, U.x, __fmul_rn(fw1, U.z)));
            float v = __fmaf_rn(fw2, U2.y, __fmaf_rn(fw0, U.y, __fmul_rn(fw1, U.w)));
            float mask = __fadd_rn(__fadd_rn(fw0, fw1), fw2);

            float x = u * (float)(tw - 1);
            float y = (1.0f - v) * (float)(th - 1);
            float x0f = fminf(fmaxf(floorf(x), 0.0f), (float)(tw - 1));
            float y0f = fminf(fmaxf(floorf(y), 0.0f), (float)(th - 1));
            int x0i = (int)x0f, y0i = (int)y0f;
            int x1i = min(x0i + 1, tw - 1);
            int y1i = min(y0i + 1, th - 1);
            float wx = fminf(fmaxf(x - x0f, 0.0f), 1.0f);
            float wy = fminf(fmaxf(y - y0f, 0.0f), 1.0f);

            int cs = th * tw;
            int b00 = y0i * tw + x0i, b01 = y0i * tw + x1i;
            int b10 = y1i * tw + x0i, b11 = y1i * tw + x1i;

            float col3[3];
            #pragma unroll
            for (int ch = 0; ch < 3; ch++) {
                const float* tc = tex + ch * cs;
                float v00 = __ldg(tc + b00), v01 = __ldg(tc + b01);
                float v10 = __ldg(tc + b10), v11 = __ldg(tc + b11);
                float cc = (v00 * (1.0f - wx) + v01 * wx) * (1.0f - wy)
                         + (v10 * (1.0f - wx) + v11 * wx) * wy;
                col3[ch] = fminf(fmaxf(cc * mask, 0.0f), 1.0f);
            }
            c0 = col3[0]; c1 = col3[1]; c2 = col3[2];
        }
        out[pix * 3 + 0] = c0;
        out[pix * 3 + 1] = c1;
        out[pix * 3 + 2] = c2;
    }
}

extern "C" void kernel_launch(void* const* d_in, const int* in_sizes, int n_in,
                              void* d_out, int out_size) {
    const float* pts   = (const float*)d_in[0];
    const int*   faces = (const int*)  d_in[1];
    const float* rot   = (const float*)d_in[2];
    const float* cpos  = (const float*)d_in[3];
    const float* cproj = (const float*)d_in[4];
    const float* uv    = (const float*)d_in[5];
    const int*   ft    = (const int*)  d_in[6];
    const float* tex   = (const float*)d_in[7];

    int P = in_sizes[0] / 3;
    int F = in_sizes[1] / 3;
    int texels = in_sizes[7] / 3;
    int tw = (int)(sqrt((double)texels) + 0.5);
    int th = texels / tw;

    float* out = (float*)d_out;
    int normal_off = HEIGHT * WIDTH * 3 + HEIGHT * WIDTH;

    face_kernel<<<1, 256>>>(pts, faces, rot, cpos, cproj, uv, ft, out, P, F, normal_off);
    // 32x32 tiles of 8x8 pixels
    raster_kernel<<<1024, 256>>>(tex, out, th, tw);
}